// round 5
// baseline (speedup 1.0000x reference)
#include <cuda_runtime.h>
#include <cuda_bf16.h>
#include <cstddef>

// Problem constants
#define BB 8
#define TT 16
#define HH 64
#define WW 64
#define CIN 32
#define FF 32
#define G4F 128
#define BN_EPS 1e-3f

// Tile: 32 wide x 16 tall, 256 threads, 2 px/thread (rows pr, pr+8)
#define TW 32
#define TH 16
#define IN_ROWS 18
#define IN_COLS 34
#define ROW_STRIDE (32 * IN_COLS)
#define SIN_FLOATS (IN_ROWS * ROW_STRIDE)   // 19584
#define SW_FLOATS  (288 * 32)               // 9216
#define SMEM_BYTES ((SIN_FLOATS + SW_FLOATS) * 4)  // 115200 B -> 2 CTA/SM

#define LSTM_GRID 256   // 8 tiles * 4 chunks * 8 batch; 296 residency available

// Scratch (allocation-free: static __device__ globals)
__device__ float g_xg[(size_t)BB * TT * HH * WW * G4F];
__device__ float g_h[2][(size_t)BB * HH * WW * FF];
__device__ float g_c[(size_t)BB * HH * WW * FF];
__device__ unsigned g_bar[TT];

__device__ __forceinline__ float hsig(float x) {
    return __saturatef(fmaf(0.2f, x, 0.5f));
}

// ---- packed f32x2 helpers ----
__device__ __forceinline__ unsigned long long pack2(float v) {
    unsigned long long r;
    asm("mov.b64 %0, {%1, %1};" : "=l"(r) : "f"(v));
    return r;
}
__device__ __forceinline__ void ffma2(unsigned long long& d,
                                      unsigned long long a,
                                      unsigned long long b) {
    asm("fma.rn.f32x2 %0, %1, %2, %3;" : "=l"(d) : "l"(a), "l"(b), "l"(d));
}
__device__ __forceinline__ void unpack2(unsigned long long p, float& lo, float& hi) {
    asm("mov.b64 {%0, %1}, %2;" : "=f"(lo), "=f"(hi) : "l"(p));
}

// Full 3x3 conv over 32 cin for 2 pixels, 32 couts. Weights fully staged.
__device__ __forceinline__ void conv_core(
    const float* __restrict__ s_in, const float* __restrict__ s_w,
    int pr, int px, unsigned long long* acc0, unsigned long long* acc1)
{
#pragma unroll
    for (int dy = 0; dy < 3; dy++) {
#pragma unroll
        for (int dx = 0; dx < 3; dx++) {
            const float* i0 = &s_in[(pr + dy) * ROW_STRIDE + (px + dx)];
            const float* i1 = i0 + 8 * ROW_STRIDE;
            const float* wb = &s_w[(dy * 3 + dx) * 32 * 32];
#pragma unroll 4
            for (int cin = 0; cin < 32; cin++) {
                unsigned long long v0 = pack2(i0[cin * IN_COLS]);
                unsigned long long v1 = pack2(i1[cin * IN_COLS]);
                const ulonglong2* w2 = (const ulonglong2*)(wb + cin * 32);
#pragma unroll
                for (int q = 0; q < 8; q++) {
                    ulonglong2 w = w2[q];
                    ffma2(acc0[q * 2 + 0], v0, w.x);
                    ffma2(acc0[q * 2 + 1], v0, w.y);
                    ffma2(acc1[q * 2 + 0], v1, w.x);
                    ffma2(acc1[q * 2 + 1], v1, w.y);
                }
            }
        }
    }
}

// Load 18x34x32 input tile into smem [row][cin][col].
template <bool CV>
__device__ __forceinline__ void load_input_tile(
    float* __restrict__ s_in, const float* __restrict__ src,
    int ty0, int tx0, int tid, int ch_stride)
{
    for (int i = tid; i < IN_ROWS * IN_COLS * 32; i += 256) {
        int cin = i & 31;
        int p   = i >> 5;
        int row = p / IN_COLS, col = p - row * IN_COLS;
        int gy = ty0 + row - 1, gx = tx0 + col - 1;
        float v = 0.f;
        if ((unsigned)gy < (unsigned)HH && (unsigned)gx < (unsigned)WW) {
            const float* ap = &src[((size_t)gy * WW + gx) * ch_stride + cin];
            v = CV ? __ldcv(ap) : __ldg(ap);
        }
        s_in[(row * 32 + cin) * IN_COLS + col] = v;
    }
}

// ---------------------------------------------------------------------------
// Kernel 1: xg = conv(x, Wx) + b, all frames. grid (8,4,128), block 256.
// ---------------------------------------------------------------------------
__global__ void __launch_bounds__(256, 2) xg_conv_kernel(
    const float* __restrict__ x, const float* __restrict__ Wx,
    const float* __restrict__ b)
{
    extern __shared__ float sm[];
    float* s_in = sm;
    float* s_w  = sm + SIN_FLOATS;

    const int tile = blockIdx.x;
    const int cc   = blockIdx.y;
    const int n    = blockIdx.z;
    const int tx0 = (tile & 1) * TW;
    const int ty0 = (tile >> 1) * TH;
    const int tid = threadIdx.x;

    load_input_tile<false>(s_in, x + (size_t)n * HH * WW * CIN, ty0, tx0, tid, CIN);
    for (int i = tid; i < 288 * 32; i += 256) {
        int k = i >> 5, co = i & 31;
        s_w[i] = Wx[k * G4F + cc * 32 + co];
    }
    __syncthreads();

    const int px = tid & 31, pr = tid >> 5;
    unsigned long long acc0[16], acc1[16];
#pragma unroll
    for (int m = 0; m < 16; m++) { acc0[m] = 0ull; acc1[m] = 0ull; }

    conv_core(s_in, s_w, pr, px, acc0, acc1);

    float a0[32], a1[32];
#pragma unroll
    for (int m = 0; m < 16; m++) {
        unpack2(acc0[m], a0[2 * m], a0[2 * m + 1]);
        unpack2(acc1[m], a1[2 * m], a1[2 * m + 1]);
    }

    const int gx = tx0 + px;
    const int gy0 = ty0 + pr, gy1 = gy0 + 8;
    float* o0 = &g_xg[(((size_t)n * HH + gy0) * WW + gx) * G4F + cc * 32];
    float* o1 = &g_xg[(((size_t)n * HH + gy1) * WW + gx) * G4F + cc * 32];
#pragma unroll
    for (int q = 0; q < 8; q++) {
        float4 bv = *(const float4*)&b[cc * 32 + q * 4];
        ((float4*)o0)[q] = make_float4(a0[q*4+0]+bv.x, a0[q*4+1]+bv.y,
                                       a0[q*4+2]+bv.z, a0[q*4+3]+bv.w);
        ((float4*)o1)[q] = make_float4(a1[q*4+0]+bv.x, a1[q*4+1]+bv.y,
                                       a1[q*4+2]+bv.z, a1[q*4+3]+bv.w);
    }
}

// ---------------------------------------------------------------------------
__global__ void bar_reset_kernel() {
    if (threadIdx.x < TT) g_bar[threadIdx.x] = 0u;
}

// ---------------------------------------------------------------------------
// Kernel 2: persistent LSTM — all 16 steps, one launch. Wh chunk staged in
// smem ONCE (t-invariant); per step only the h tile is reloaded.
// grid = 256 CTAs (co-resident @ 2 CTA/SM). block 256, 2 px/thread.
// ---------------------------------------------------------------------------
__global__ void __launch_bounds__(256, 2) lstm_persistent(
    const float* __restrict__ Wh,
    const float* __restrict__ gamma, const float* __restrict__ beta,
    const float* __restrict__ mmean, const float* __restrict__ mvar,
    float* __restrict__ out)
{
    extern __shared__ float sm[];
    float* s_in = sm;
    float* s_w  = sm + SIN_FLOATS;

    const int cta  = blockIdx.x;
    const int tile = cta & 7;
    const int fc   = (cta >> 3) & 3;
    const int bb   = cta >> 5;
    const int tx0 = (tile & 1) * TW;
    const int ty0 = (tile >> 1) * TH;
    const int tid = threadIdx.x;
    const int px = tid & 31, pr = tid >> 5;
    const int gx = tx0 + px;
    const int gy0 = ty0 + pr;

    // Stage gate-interleaved Wh chunk ONCE: col = g*8+j -> cout = g*32+fc*8+j
    for (int i = tid; i < 288 * 32; i += 256) {
        int k = i >> 5, col = i & 31;
        int cout = (col >> 3) * 32 + fc * 8 + (col & 7);
        s_w[i] = Wh[k * G4F + cout];
    }

    // BN constants (loop-invariant)
    float inv[8], off[8];
#pragma unroll
    for (int j = 0; j < 8; j++) {
        int f = fc * 8 + j;
        inv[j] = gamma[f] * rsqrtf(mvar[f] + BN_EPS);
        off[j] = beta[f] - mmean[f] * inv[j];
    }

    for (int t = 0; t < TT; t++) {
        unsigned long long acc0[16], acc1[16];
#pragma unroll
        for (int m = 0; m < 16; m++) { acc0[m] = 0ull; acc1[m] = 0ull; }

        if (t > 0) {
            // h tile written by other SMs last step -> bypass L1
            const float* hin = g_h[(t + 1) & 1] + (size_t)bb * HH * WW * FF;
            load_input_tile<true>(s_in, hin, ty0, tx0, tid, FF);
            __syncthreads();
            conv_core(s_in, s_w, pr, px, acc0, acc1);
        }

        float a0[32], a1[32];
#pragma unroll
        for (int m = 0; m < 16; m++) {
            unpack2(acc0[m], a0[2 * m], a0[2 * m + 1]);
            unpack2(acc1[m], a1[2 * m], a1[2 * m + 1]);
        }

#pragma unroll
        for (int p = 0; p < 2; p++) {
            const float* a = p ? a1 : a0;
            const int gy = gy0 + p * 8;
            const size_t pix   = (size_t)bb * HH * WW + (size_t)gy * WW + gx;
            const size_t frame = (size_t)(bb * TT + t) * HH * WW + (size_t)gy * WW + gx;
            const float* xgp = &g_xg[frame * G4F];
            float* cst = &g_c[pix * FF + fc * 8];
            float* hst = &g_h[t & 1][pix * FF + fc * 8];
            float* op  = &out[frame * FF + fc * 8];

            float coldv[8] = {0,0,0,0,0,0,0,0};
            if (t > 0) {
                float4 c0 = ((const float4*)cst)[0];
                float4 c1 = ((const float4*)cst)[1];
                coldv[0]=c0.x; coldv[1]=c0.y; coldv[2]=c0.z; coldv[3]=c0.w;
                coldv[4]=c1.x; coldv[5]=c1.y; coldv[6]=c1.z; coldv[7]=c1.w;
            }

            float cv[8], hv[8], ov[8];
#pragma unroll
            for (int j = 0; j < 8; j++) {
                int f = fc * 8 + j;
                float gi = a[0 * 8 + j] + __ldg(&xgp[0 * 32 + f]);
                float gf = a[1 * 8 + j] + __ldg(&xgp[1 * 32 + f]);
                float gc = a[2 * 8 + j] + __ldg(&xgp[2 * 32 + f]);
                float go = a[3 * 8 + j] + __ldg(&xgp[3 * 32 + f]);
                gi = hsig(gi); gf = hsig(gf); go = hsig(go);
                float cn = gf * coldv[j] + gi * tanhf(gc);
                float h  = go * tanhf(cn);
                cv[j] = cn; hv[j] = h;
                ov[j] = fmaf(h, inv[j], off[j]);
            }
            ((float4*)cst)[0] = make_float4(cv[0], cv[1], cv[2], cv[3]);
            ((float4*)cst)[1] = make_float4(cv[4], cv[5], cv[6], cv[7]);
            ((float4*)hst)[0] = make_float4(hv[0], hv[1], hv[2], hv[3]);
            ((float4*)hst)[1] = make_float4(hv[4], hv[5], hv[6], hv[7]);
            ((float4*)op)[0]  = make_float4(ov[0], ov[1], ov[2], ov[3]);
            ((float4*)op)[1]  = make_float4(ov[4], ov[5], ov[6], ov[7]);
        }

        // Grid-wide barrier: publish h_t before step t+1
        if (t < TT - 1) {
            __threadfence();
            __syncthreads();
            if (tid == 0) {
                atomicAdd(&g_bar[t], 1u);
                while (*((volatile unsigned*)&g_bar[t]) < (unsigned)LSTM_GRID)
                    __nanosleep(64);
            }
            __syncthreads();
            __threadfence();
        }
    }
}

// ---------------------------------------------------------------------------
extern "C" void kernel_launch(void* const* d_in, const int* in_sizes, int n_in,
                              void* d_out, int out_size)
{
    const float* x     = (const float*)d_in[0];
    const float* Wx    = (const float*)d_in[1];
    const float* Wh    = (const float*)d_in[2];
    const float* b     = (const float*)d_in[3];
    const float* gamma = (const float*)d_in[4];
    const float* beta  = (const float*)d_in[5];
    const float* mmean = (const float*)d_in[6];
    const float* mvar  = (const float*)d_in[7];
    float* out = (float*)d_out;

    cudaFuncSetAttribute(xg_conv_kernel,
        cudaFuncAttributeMaxDynamicSharedMemorySize, SMEM_BYTES);
    cudaFuncSetAttribute(lstm_persistent,
        cudaFuncAttributeMaxDynamicSharedMemorySize, SMEM_BYTES);

    {
        dim3 grid(8, 4, BB * TT);
        xg_conv_kernel<<<grid, 256, SMEM_BYTES>>>(x, Wx, b);
    }
    bar_reset_kernel<<<1, 32>>>();
    lstm_persistent<<<LSTM_GRID, 256, SMEM_BYTES>>>(
        Wh, gamma, beta, mmean, mvar, out);
}

// round 7
// speedup vs baseline: 1.0879x; 1.0879x over previous
#include <cuda_runtime.h>
#include <cuda_bf16.h>
#include <mma.h>
#include <cstdint>
#include <cstddef>

using namespace nvcuda;

// Problem constants
#define BB 8
#define TT 16
#define HH 64
#define WW 64
#define CIN 32
#define FF 32
#define G4F 128
#define BN_EPS 1e-3f

// ======================= device scratch (no allocs) ========================
__device__ float g_xg[(size_t)BB * TT * HH * WW * G4F];
__device__ float g_h[2][(size_t)BB * HH * WW * FF];
__device__ float g_c[(size_t)BB * HH * WW * FF];
__device__ unsigned g_bar[TT];
// Pre-split/transposed/padded B operands: [6 passes][128 n][64 k] bf16
__device__ __nv_bfloat16 g_Bh[6 * 128 * 64];
__device__ __nv_bfloat16 g_Bl[6 * 128 * 64];

// ======================= helpers ===========================================
__device__ __forceinline__ float hsig(float x) {
    return __saturatef(fmaf(0.2f, x, 0.5f));
}
__device__ __forceinline__ unsigned long long pack2(float v) {
    unsigned long long r;
    asm("mov.b64 %0, {%1, %1};" : "=l"(r) : "f"(v));
    return r;
}
__device__ __forceinline__ void ffma2(unsigned long long& d,
                                      unsigned long long a,
                                      unsigned long long b) {
    asm("fma.rn.f32x2 %0, %1, %2, %3;" : "=l"(d) : "l"(a), "l"(b), "l"(d));
}
__device__ __forceinline__ void unpack2(unsigned long long p, float& lo, float& hi) {
    asm("mov.b64 {%0, %1}, %2;" : "=f"(lo), "=f"(hi) : "l"(p));
}

// ===========================================================================
// Kernel 0: build split/transposed/padded B operands.
// pass = dy*2 + half.
//  half0: k<32 -> Wx[dy,kw=0][k][n]; k>=32 -> Wx[dy,kw=1][k-32][n]
//  half1: k<32 -> Wx[dy,kw=2][k][n]; k>=32 -> 0
// ===========================================================================
__global__ void build_B_kernel(const float* __restrict__ Wx) {
    int idx = blockIdx.x * blockDim.x + threadIdx.x;
    if (idx >= 6 * 128 * 64) return;
    int pass = idx >> 13;
    int rem  = idx & 8191;
    int n    = rem >> 6;
    int k    = rem & 63;
    int dy   = pass >> 1;
    int half = pass & 1;
    float w = 0.f;
    if (half == 0) {
        int kw = (k < 32) ? 0 : 1;
        int cin = k & 31;
        w = Wx[((size_t)((dy * 3 + kw) * CIN + cin)) * G4F + n];
    } else if (k < 32) {
        w = Wx[((size_t)((dy * 3 + 2) * CIN + k)) * G4F + n];
    }
    __nv_bfloat16 hi = __float2bfloat16(w);
    __nv_bfloat16 lo = __float2bfloat16(w - __bfloat162float(hi));
    g_Bh[idx] = hi;
    g_Bl[idx] = lo;
}

// ===========================================================================
// Kernel 1: xg = conv(x,Wx)+b via wmma (HMMA bf16, bf16x3 split, fp32 acc).
// CTA = (row-pair rp, frame n): M=128 px (2 rows x 64 cols) x N=128 couts.
// K = 288 as 6 passes of K=64 (dy x {kw01, kw2+zero-pad}).
// 512 threads = 16 warps of 32x32 output tiles.
// A is read directly from the staged raw tile via shifted pointers:
//   A(m,k) lives at raw[(base_slot(m) + (kc>=2))*48 + (kc&1)*16 + kk], ldm=48.
// ===========================================================================
#define XG_SLOT 48
#define XG_OFF_RAWH 0
#define XG_OFF_RAWL 25440                    // 265*48*2
#define XG_OFF_BH   50880
#define XG_OFF_BL   71360                    // + 128*80*2
#define XG_SMEM     91840

__global__ void __launch_bounds__(512, 1) xg_wmma_kernel(
    const float* __restrict__ x, const float* __restrict__ bias)
{
    extern __shared__ char smem[];
    __nv_bfloat16* rawh = (__nv_bfloat16*)(smem + XG_OFF_RAWH);
    __nv_bfloat16* rawl = (__nv_bfloat16*)(smem + XG_OFF_RAWL);
    __nv_bfloat16* sBh  = (__nv_bfloat16*)(smem + XG_OFF_BH);
    __nv_bfloat16* sBl  = (__nv_bfloat16*)(smem + XG_OFF_BL);

    const int tid = threadIdx.x;
    const int wid = tid >> 5;
    const int rp = blockIdx.x;           // 0..31 (row pair)
    const int n  = blockIdx.y;           // 0..127 (frame)
    const int r0 = rp * 2;

    // --- stage raw input: 4 rows x 66 cols (+1 guard slot) x 32 cin, split
    {
        const float* xin = x + (size_t)n * HH * WW * CIN;
        for (int i = tid; i < 265 * 32; i += 512) {
            int cin = i & 31;
            int p   = i >> 5;            // slot 0..264 (264 = zero guard)
            float v = 0.f;
            if (p < 264) {
                int dyrow = p / 66, sc = p - dyrow * 66;
                int gy = r0 + dyrow - 1, gx = sc - 1;
                if ((unsigned)gy < (unsigned)HH && (unsigned)gx < (unsigned)WW)
                    v = __ldg(&xin[((size_t)gy * WW + gx) * CIN + cin]);
            }
            __nv_bfloat16 hi = __float2bfloat16(v);
            __nv_bfloat16 lo = __float2bfloat16(v - __bfloat162float(hi));
            rawh[p * XG_SLOT + cin] = hi;
            rawl[p * XG_SLOT + cin] = lo;
        }
    }

    const int wm = wid & 3;              // m-tile 0..3
    const int wn = wid >> 2;             // n-tile 0..3
    const int m0 = wm * 32;
    const int n0 = wn * 32;

    wmma::fragment<wmma::accumulator, 16, 16, 16, float> acc[2][2];
#pragma unroll
    for (int i = 0; i < 2; i++)
#pragma unroll
        for (int j = 0; j < 2; j++)
            wmma::fill_fragment(acc[i][j], 0.f);

    for (int pass = 0; pass < 6; pass++) {
        const int dy = pass >> 1, half = pass & 1;

        __syncthreads();   // previous-pass MMAs done before restaging B
        // stage B: both precisions, [128 n][80] rows (uint4 = 8 bf16)
        for (int i = tid; i < 2048; i += 512) {
            int prec = i >> 10;
            int j = i & 1023;
            int nn = j >> 3, c8 = j & 7;
            const __nv_bfloat16* src =
                (prec ? g_Bl : g_Bh) + (size_t)pass * 8192 + nn * 64 + c8 * 8;
            __nv_bfloat16* dst = (prec ? sBl : sBh) + nn * 80 + c8 * 8;
            *(uint4*)dst = __ldg((const uint4*)src);
        }
        __syncthreads();

#pragma unroll
        for (int kc = 0; kc < 4; kc++) {
            wmma::fragment<wmma::matrix_a, 16, 16, 16, __nv_bfloat16,
                           wmma::row_major> ah[2], al[2];
            wmma::fragment<wmma::matrix_b, 16, 16, 16, __nv_bfloat16,
                           wmma::col_major> bh[2], bl[2];
#pragma unroll
            for (int i = 0; i < 2; i++) {
                int m = m0 + i * 16;
                int r = m >> 6, cblk = m & 63;
                int base = (r + dy) * 66 + cblk + 2 * half + (kc >> 1);
                const __nv_bfloat16* pa_h = rawh + base * XG_SLOT + (kc & 1) * 16;
                const __nv_bfloat16* pa_l = rawl + base * XG_SLOT + (kc & 1) * 16;
                wmma::load_matrix_sync(ah[i], pa_h, XG_SLOT);
                wmma::load_matrix_sync(al[i], pa_l, XG_SLOT);
            }
#pragma unroll
            for (int j = 0; j < 2; j++) {
                const __nv_bfloat16* pb_h = sBh + (n0 + j * 16) * 80 + kc * 16;
                const __nv_bfloat16* pb_l = sBl + (n0 + j * 16) * 80 + kc * 16;
                wmma::load_matrix_sync(bh[j], pb_h, 80);
                wmma::load_matrix_sync(bl[j], pb_l, 80);
            }
#pragma unroll
            for (int i = 0; i < 2; i++)
#pragma unroll
                for (int j = 0; j < 2; j++) {
                    wmma::mma_sync(acc[i][j], ah[i], bh[j], acc[i][j]);
                    wmma::mma_sync(acc[i][j], ah[i], bl[j], acc[i][j]);
                    wmma::mma_sync(acc[i][j], al[i], bh[j], acc[i][j]);
                }
        }
    }

    // --- epilogue: acc -> smem scratch (fp32 [128][132]) -> +bias -> gmem
    __syncthreads();
    float* scratch = (float*)smem;
#pragma unroll
    for (int i = 0; i < 2; i++)
#pragma unroll
        for (int j = 0; j < 2; j++)
            wmma::store_matrix_sync(
                scratch + (size_t)(m0 + i * 16) * 132 + (n0 + j * 16),
                acc[i][j], 132, wmma::mem_row_major);
    __syncthreads();

    for (int i = tid; i < 4096; i += 512) {
        int pix = i >> 5, q = i & 31;
        float4 v = *(const float4*)&scratch[pix * 132 + q * 4];
        float4 bv = *(const float4*)&bias[q * 4];
        v.x += bv.x; v.y += bv.y; v.z += bv.z; v.w += bv.w;
        int r = pix >> 6, c = pix & 63;
        float* op = &g_xg[(((size_t)n * HH + r0 + r) * WW + c) * G4F + q * 4];
        *(float4*)op = v;
    }
}

// ===========================================================================
// LSTM side: proven R4 configuration (tap-streamed weights, 86.5KB smem,
// 2 CTA/SM, persistent over 16 steps with software grid barrier).
// ===========================================================================
#define TW 32
#define TH 16
#define IN_ROWS 18
#define IN_COLS 34
#define ROW_STRIDE (32 * IN_COLS)
#define SIN_FLOATS (IN_ROWS * ROW_STRIDE)     // 19584
#define SWBUF_FLOATS (2 * 32 * 32)            // 2048
#define LS_SMEM ((SIN_FLOATS + SWBUF_FLOATS) * 4)  // 86528
#define LSTM_GRID 256

__device__ __forceinline__ void conv_tap(
    const float* __restrict__ s_in, const float* __restrict__ wb,
    int pr, int px, int dy, int dx,
    unsigned long long* acc0, unsigned long long* acc1)
{
    const float* i0 = &s_in[(pr + dy) * ROW_STRIDE + (px + dx)];
    const float* i1 = i0 + 8 * ROW_STRIDE;
#pragma unroll 4
    for (int cin = 0; cin < 32; cin++) {
        unsigned long long v0 = pack2(i0[cin * IN_COLS]);
        unsigned long long v1 = pack2(i1[cin * IN_COLS]);
        const ulonglong2* w2 = (const ulonglong2*)(wb + cin * 32);
#pragma unroll
        for (int q = 0; q < 8; q++) {
            ulonglong2 w = w2[q];
            ffma2(acc0[q * 2 + 0], v0, w.x);
            ffma2(acc0[q * 2 + 1], v0, w.y);
            ffma2(acc1[q * 2 + 0], v1, w.x);
            ffma2(acc1[q * 2 + 1], v1, w.y);
        }
    }
}

__device__ __forceinline__ void load_tap_lstm(
    float* __restrict__ dst, const float* __restrict__ Wh, int kk, int fc, int tid)
{
    int cin = tid >> 3, col0 = (tid & 7) * 4;
    int cout0 = (col0 >> 3) * 32 + fc * 8 + (col0 & 7);
    float4 w = *(const float4*)&Wh[((size_t)(kk * CIN + cin)) * G4F + cout0];
    *(float4*)&dst[cin * 32 + col0] = w;
}

__device__ __forceinline__ void load_h_tile(
    float* __restrict__ s_in, const float* __restrict__ src,
    int ty0, int tx0, int tid)
{
    for (int i = tid; i < IN_ROWS * IN_COLS * 32; i += 256) {
        int cin = i & 31;
        int p   = i >> 5;
        int row = p / IN_COLS, col = p - row * IN_COLS;
        int gy = ty0 + row - 1, gx = tx0 + col - 1;
        float v = 0.f;
        if ((unsigned)gy < (unsigned)HH && (unsigned)gx < (unsigned)WW)
            v = __ldcv(&src[((size_t)gy * WW + gx) * FF + cin]);
        s_in[(row * 32 + cin) * IN_COLS + col] = v;
    }
}

__global__ void bar_reset_kernel() {
    if (threadIdx.x < TT) g_bar[threadIdx.x] = 0u;
}

__global__ void __launch_bounds__(256, 2) lstm_persistent(
    const float* __restrict__ Wh,
    const float* __restrict__ gamma, const float* __restrict__ beta,
    const float* __restrict__ mmean, const float* __restrict__ mvar,
    float* __restrict__ out)
{
    extern __shared__ float sm[];
    float* s_in = sm;
    float* s_w  = sm + SIN_FLOATS;

    const int cta  = blockIdx.x;
    const int tile = cta & 7;
    const int fc   = (cta >> 3) & 3;
    const int bb   = cta >> 5;
    const int tx0 = (tile & 1) * TW;
    const int ty0 = (tile >> 1) * TH;
    const int tid = threadIdx.x;
    const int px = tid & 31, pr = tid >> 5;
    const int gx = tx0 + px;
    const int gy0 = ty0 + pr;

    float inv[8], off[8];
#pragma unroll
    for (int j = 0; j < 8; j++) {
        int f = fc * 8 + j;
        inv[j] = gamma[f] * rsqrtf(mvar[f] + BN_EPS);
        off[j] = beta[f] - mmean[f] * inv[j];
    }

    for (int t = 0; t < TT; t++) {
        unsigned long long acc0[16], acc1[16];
#pragma unroll
        for (int m = 0; m < 16; m++) { acc0[m] = 0ull; acc1[m] = 0ull; }

        if (t > 0) {
            const float* hin = g_h[(t + 1) & 1] + (size_t)bb * HH * WW * FF;
            load_h_tile(s_in, hin, ty0, tx0, tid);
            load_tap_lstm(s_w, Wh, 0, fc, tid);
            __syncthreads();
#pragma unroll
            for (int tap = 0; tap < 9; tap++) {
                if (tap < 8)
                    load_tap_lstm(&s_w[((tap + 1) & 1) * 1024], Wh, tap + 1, fc, tid);
                conv_tap(s_in, &s_w[(tap & 1) * 1024], pr, px, tap / 3, tap % 3,
                         acc0, acc1);
                __syncthreads();
            }
        }

        float a0[32], a1[32];
#pragma unroll
        for (int m = 0; m < 16; m++) {
            unpack2(acc0[m], a0[2 * m], a0[2 * m + 1]);
            unpack2(acc1[m], a1[2 * m], a1[2 * m + 1]);
        }

#pragma unroll
        for (int p = 0; p < 2; p++) {
            const float* a = p ? a1 : a0;
            const int gy = gy0 + p * 8;
            const size_t pix   = (size_t)bb * HH * WW + (size_t)gy * WW + gx;
            const size_t frame = (size_t)(bb * TT + t) * HH * WW + (size_t)gy * WW + gx;
            const float* xgp = &g_xg[frame * G4F];
            float* cst = &g_c[pix * FF + fc * 8];
            float* hst = &g_h[t & 1][pix * FF + fc * 8];
            float* op  = &out[frame * FF + fc * 8];

            float coldv[8] = {0,0,0,0,0,0,0,0};
            if (t > 0) {
                float4 c0 = ((const float4*)cst)[0];
                float4 c1 = ((const float4*)cst)[1];
                coldv[0]=c0.x; coldv[1]=c0.y; coldv[2]=c0.z; coldv[3]=c0.w;
                coldv[4]=c1.x; coldv[5]=c1.y; coldv[6]=c1.z; coldv[7]=c1.w;
            }

            float cv[8], hv[8], ov[8];
#pragma unroll
            for (int j = 0; j < 8; j++) {
                int f = fc * 8 + j;
                float gi = a[0 * 8 + j] + __ldg(&xgp[0 * 32 + f]);
                float gf = a[1 * 8 + j] + __ldg(&xgp[1 * 32 + f]);
                float gc = a[2 * 8 + j] + __ldg(&xgp[2 * 32 + f]);
                float go = a[3 * 8 + j] + __ldg(&xgp[3 * 32 + f]);
                gi = hsig(gi); gf = hsig(gf); go = hsig(go);
                float cn = gf * coldv[j] + gi * tanhf(gc);
                float h  = go * tanhf(cn);
                cv[j] = cn; hv[j] = h;
                ov[j] = fmaf(h, inv[j], off[j]);
            }
            ((float4*)cst)[0] = make_float4(cv[0], cv[1], cv[2], cv[3]);
            ((float4*)cst)[1] = make_float4(cv[4], cv[5], cv[6], cv[7]);
            ((float4*)hst)[0] = make_float4(hv[0], hv[1], hv[2], hv[3]);
            ((float4*)hst)[1] = make_float4(hv[4], hv[5], hv[6], hv[7]);
            ((float4*)op)[0]  = make_float4(ov[0], ov[1], ov[2], ov[3]);
            ((float4*)op)[1]  = make_float4(ov[4], ov[5], ov[6], ov[7]);
        }

        if (t < TT - 1) {
            __threadfence();
            __syncthreads();
            if (tid == 0) {
                atomicAdd(&g_bar[t], 1u);
                while (*((volatile unsigned*)&g_bar[t]) < (unsigned)LSTM_GRID)
                    __nanosleep(64);
            }
            __syncthreads();
            __threadfence();
        }
    }
}

// ===========================================================================
extern "C" void kernel_launch(void* const* d_in, const int* in_sizes, int n_in,
                              void* d_out, int out_size)
{
    const float* x     = (const float*)d_in[0];
    const float* Wx    = (const float*)d_in[1];
    const float* Wh    = (const float*)d_in[2];
    const float* b     = (const float*)d_in[3];
    const float* gamma = (const float*)d_in[4];
    const float* beta  = (const float*)d_in[5];
    const float* mmean = (const float*)d_in[6];
    const float* mvar  = (const float*)d_in[7];
    float* out = (float*)d_out;

    cudaFuncSetAttribute(xg_wmma_kernel,
        cudaFuncAttributeMaxDynamicSharedMemorySize, XG_SMEM);
    cudaFuncSetAttribute(lstm_persistent,
        cudaFuncAttributeMaxDynamicSharedMemorySize, LS_SMEM);

    // 0) split/transpose/pad weight operands
    build_B_kernel<<<192, 256>>>(Wx);
    // 1) input-to-gate conv on tensor cores (wmma/HMMA)
    {
        dim3 grid(32, BB * TT);
        xg_wmma_kernel<<<grid, 512, XG_SMEM>>>(x, b);
    }
    // 2) persistent recurrence
    bar_reset_kernel<<<1, 32>>>();
    lstm_persistent<<<LSTM_GRID, 256, LS_SMEM>>>(
        Wh, gamma, beta, mmean, mvar, out);
}